// round 2
// baseline (speedup 1.0000x reference)
#include <cuda_runtime.h>
#include <cstdint>
#include <math.h>

#define DIMN 768
#define HIDN 1536
#define NB 8
#define NS 2048
#define NTOK (NB*NS)

static __device__ __forceinline__ float geluf(float x) {
    return 0.5f * x * (1.0f + erff(x * 0.70710678118654752f));
}

#define INV_SCALE_F 0.03608439182435161f   // 1/sqrt(768)

// ---------------- scratch (static device globals; allocation-free) ----------
__device__ float g_Q[(long)NTOK * DIMN];
__device__ float g_K[(long)NTOK * DIMN];
__device__ float g_V[(long)NTOK * DIMN];
__device__ float g_alpha[(long)NB * NS * NS];
__device__ float g_attn[(long)NTOK * DIMN];
__device__ float g_t1[(long)NTOK * DIMN];
__device__ float g_h[(long)NTOK * DIMN];
__device__ float g_mlp[(long)NTOK * HIDN];
__device__ float g_t2[(long)NTOK * DIMN];

// ---------------- small PTX helpers -----------------------------------------
__device__ __forceinline__ void cpa16(float* dst, const float* src) {
    unsigned d = (unsigned)__cvta_generic_to_shared(dst);
    asm volatile("cp.async.cg.shared.global [%0], [%1], 16;" :: "r"(d), "l"(src));
}
__device__ __forceinline__ void cp_commit() { asm volatile("cp.async.commit_group;"); }
template<int N> __device__ __forceinline__ void cp_wait() {
    asm volatile("cp.async.wait_group %0;" :: "n"(N));
}
__device__ __forceinline__ uint32_t f2tf32(float f) {
    uint32_t r; asm("cvt.rna.tf32.f32 %0, %1;" : "=r"(r) : "f"(f)); return r;
}
__device__ __forceinline__ void mma_tf32(float* c, const uint32_t* a, const uint32_t* b) {
    asm volatile(
        "mma.sync.aligned.m16n8k8.row.col.f32.tf32.tf32.f32 "
        "{%0,%1,%2,%3}, {%4,%5,%6,%7}, {%8,%9}, {%0,%1,%2,%3};"
        : "+f"(c[0]), "+f"(c[1]), "+f"(c[2]), "+f"(c[3])
        : "r"(a[0]), "r"(a[1]), "r"(a[2]), "r"(a[3]), "r"(b[0]), "r"(b[1]));
}

// ---------------- GEMM: C[M,N] = A[M,K] @ op(B) + epilogue -------------------
// BT=true : B stored [N,K] (use B^T)  — "NT"
// BT=false: B stored [K,N]            — "NN"
// CTA tile 128x256, 8 warps of 64x64, BK=32, double buffered cp.async.
enum { EPI_NONE = 0, EPI_SCALE = 1, EPI_BIAS = 2, EPI_BIAS_RESID = 3, EPI_BIAS_GELU = 4 };

#define ALD 36
#define ASZ (128 * ALD)
#define BSZ_NT (256 * 36)
#define BSZ_NN (32 * 264)

template<bool BT>
__device__ __forceinline__ void load_tiles(const float* __restrict__ A, int lda,
                                           const float* __restrict__ Bg, int ldb,
                                           int m0, int n0, int kb,
                                           float* __restrict__ As, float* __restrict__ Bs,
                                           int tid) {
    // A tile: 128 rows x 32 k (row-major global)
    {
        const float* src = A + (long)m0 * lda + kb * 32;
        #pragma unroll
        for (int i = 0; i < 4; i++) {
            int idx = tid + i * 256;
            int r = idx >> 3, c = (idx & 7) * 4;
            cpa16(As + r * ALD + c, src + (long)r * lda + c);
        }
    }
    if (BT) {
        // B tile: 256 n-rows x 32 k
        const float* src = Bg + (long)n0 * ldb + kb * 32;
        #pragma unroll
        for (int i = 0; i < 8; i++) {
            int idx = tid + i * 256;
            int r = idx >> 3, c = (idx & 7) * 4;
            cpa16(Bs + r * 36 + c, src + (long)r * ldb + c);
        }
    } else {
        // B tile: 32 k-rows x 256 n
        const float* src = Bg + (long)(kb * 32) * ldb + n0;
        #pragma unroll
        for (int i = 0; i < 8; i++) {
            int idx = tid + i * 256;
            int r = idx >> 6, c = (idx & 63) * 4;
            cpa16(Bs + r * 264 + c, src + (long)r * ldb + c);
        }
    }
}

template<int EPI, bool BT>
__global__ __launch_bounds__(256, 1)
void gemm_kernel(const float* __restrict__ A, int lda, long sA,
                 const float* __restrict__ Bg, int ldb, long sB,
                 float* __restrict__ C, int ldc, long sC,
                 const float* __restrict__ bias,
                 const float* __restrict__ resid,
                 int Kdim) {
    extern __shared__ float smem[];
    const int BSZ = BT ? BSZ_NT : BSZ_NN;
    float* As = smem;              // [2][ASZ]
    float* Bs = smem + 2 * ASZ;    // [2][BSZ]

    const int tid = threadIdx.x;
    const long bz = blockIdx.z;
    A += bz * sA; Bg += bz * sB; C += bz * sC;

    const int m0 = blockIdx.y * 128;
    const int n0 = blockIdx.x * 256;

    const int lane = tid & 31;
    const int g = lane >> 2, tg = lane & 3;
    const int wid = tid >> 5;
    const int wm0 = (wid & 1) * 64;
    const int wn0 = (wid >> 1) * 64;

    float acc[4][8][4];
    #pragma unroll
    for (int i = 0; i < 4; i++)
        #pragma unroll
        for (int j = 0; j < 8; j++)
            #pragma unroll
            for (int r = 0; r < 4; r++) acc[i][j][r] = 0.0f;

    const int nk = Kdim >> 5;
    load_tiles<BT>(A, lda, Bg, ldb, m0, n0, 0, As, Bs, tid);
    cp_commit();

    for (int kb = 0; kb < nk; ++kb) {
        const int st = kb & 1;
        if (kb + 1 < nk) {
            load_tiles<BT>(A, lda, Bg, ldb, m0, n0, kb + 1,
                           As + (st ^ 1) * ASZ, Bs + (st ^ 1) * BSZ, tid);
            cp_commit();
            cp_wait<1>();
        } else {
            cp_wait<0>();
        }
        __syncthreads();

        const float* Ab = As + st * ASZ;
        const float* Bb = Bs + st * BSZ;

        #pragma unroll
        for (int kk = 0; kk < 4; kk++) {
            uint32_t af[4][4];
            #pragma unroll
            for (int mi = 0; mi < 4; mi++) {
                const float* a = Ab + (wm0 + mi * 16 + g) * ALD + kk * 8 + tg;
                af[mi][0] = f2tf32(a[0]);
                af[mi][1] = f2tf32(a[8 * ALD]);
                af[mi][2] = f2tf32(a[4]);
                af[mi][3] = f2tf32(a[8 * ALD + 4]);
            }
            uint32_t bf[8][2];
            #pragma unroll
            for (int nj = 0; nj < 8; nj++) {
                if (BT) {
                    const float* b = Bb + (wn0 + nj * 8 + g) * 36 + kk * 8 + tg;
                    bf[nj][0] = f2tf32(b[0]);
                    bf[nj][1] = f2tf32(b[4]);
                } else {
                    const float* b = Bb + (kk * 8 + tg) * 264 + wn0 + nj * 8 + g;
                    bf[nj][0] = f2tf32(b[0]);
                    bf[nj][1] = f2tf32(b[4 * 264]);
                }
            }
            #pragma unroll
            for (int mi = 0; mi < 4; mi++)
                #pragma unroll
                for (int nj = 0; nj < 8; nj++)
                    mma_tf32(acc[mi][nj], af[mi], bf[nj]);
        }
        __syncthreads();
    }

    // epilogue
    #pragma unroll
    for (int mi = 0; mi < 4; mi++) {
        #pragma unroll
        for (int r2 = 0; r2 < 2; r2++) {
            const int row = m0 + wm0 + mi * 16 + g + r2 * 8;
            #pragma unroll
            for (int nj = 0; nj < 8; nj++) {
                const int col = n0 + wn0 + nj * 8 + 2 * tg;
                float v0 = acc[mi][nj][r2 * 2 + 0];
                float v1 = acc[mi][nj][r2 * 2 + 1];
                const long off = (long)row * ldc + col;
                if (EPI == EPI_SCALE) { v0 *= INV_SCALE_F; v1 *= INV_SCALE_F; }
                if (EPI == EPI_BIAS || EPI == EPI_BIAS_RESID || EPI == EPI_BIAS_GELU) {
                    v0 += bias[col]; v1 += bias[col + 1];
                }
                if (EPI == EPI_BIAS_RESID) {
                    float2 rr = *(const float2*)(resid + off);
                    v0 += rr.x; v1 += rr.y;
                }
                if (EPI == EPI_BIAS_GELU) { v0 = geluf(v0); v1 = geluf(v1); }
                float2 o; o.x = v0; o.y = v1;
                *(float2*)(C + off) = o;
            }
        }
    }
}

// ---------------- softmax over rows of length 2048 ---------------------------
__global__ __launch_bounds__(256)
void softmax_kernel(float* __restrict__ a) {
    __shared__ float red[8];
    __shared__ float bc;
    const int t = threadIdx.x;
    const int lane = t & 31, wid = t >> 5;
    float* p = a + (long)blockIdx.x * 2048;

    float4 x0 = reinterpret_cast<float4*>(p)[t];
    float4 x1 = reinterpret_cast<float4*>(p)[t + 256];

    float m = fmaxf(fmaxf(fmaxf(x0.x, x0.y), fmaxf(x0.z, x0.w)),
                    fmaxf(fmaxf(x1.x, x1.y), fmaxf(x1.z, x1.w)));
    #pragma unroll
    for (int o = 16; o > 0; o >>= 1) m = fmaxf(m, __shfl_xor_sync(0xffffffffu, m, o));
    if (lane == 0) red[wid] = m;
    __syncthreads();
    if (t == 0) {
        float mm = red[0];
        #pragma unroll
        for (int i = 1; i < 8; i++) mm = fmaxf(mm, red[i]);
        bc = mm;
    }
    __syncthreads();
    m = bc;

    float e[8];
    e[0] = __expf(x0.x - m); e[1] = __expf(x0.y - m);
    e[2] = __expf(x0.z - m); e[3] = __expf(x0.w - m);
    e[4] = __expf(x1.x - m); e[5] = __expf(x1.y - m);
    e[6] = __expf(x1.z - m); e[7] = __expf(x1.w - m);
    float s = (e[0] + e[1]) + (e[2] + e[3]) + (e[4] + e[5]) + (e[6] + e[7]);
    #pragma unroll
    for (int o = 16; o > 0; o >>= 1) s += __shfl_xor_sync(0xffffffffu, s, o);
    if (lane == 0) red[wid] = s;
    __syncthreads();
    if (t == 0) {
        float ss = 0.0f;
        #pragma unroll
        for (int i = 0; i < 8; i++) ss += red[i];
        bc = 1.0f / ss;
    }
    __syncthreads();
    const float inv = bc;

    x0.x = e[0] * inv; x0.y = e[1] * inv; x0.z = e[2] * inv; x0.w = e[3] * inv;
    x1.x = e[4] * inv; x1.y = e[5] * inv; x1.z = e[6] * inv; x1.w = e[7] * inv;
    reinterpret_cast<float4*>(p)[t]       = x0;
    reinterpret_cast<float4*>(p)[t + 256] = x1;
}

// ---------------- LayerNorm over rows of 768 (one warp per row) --------------
__global__ __launch_bounds__(128)
void ln_kernel(const float* __restrict__ in, const float* __restrict__ gamma,
               const float* __restrict__ beta, float* __restrict__ out) {
    const int wid = threadIdx.x >> 5, lane = threadIdx.x & 31;
    const long row = (long)blockIdx.x * 4 + wid;
    const float4* p = (const float4*)(in + row * DIMN);

    float4 v[6];
    float s = 0.0f, sq = 0.0f;
    #pragma unroll
    for (int j = 0; j < 6; j++) {
        v[j] = p[lane + 32 * j];
        s  += (v[j].x + v[j].y) + (v[j].z + v[j].w);
        sq += (v[j].x * v[j].x + v[j].y * v[j].y) + (v[j].z * v[j].z + v[j].w * v[j].w);
    }
    #pragma unroll
    for (int o = 16; o > 0; o >>= 1) {
        s  += __shfl_xor_sync(0xffffffffu, s, o);
        sq += __shfl_xor_sync(0xffffffffu, sq, o);
    }
    const float mean = s * (1.0f / DIMN);
    const float var  = sq * (1.0f / DIMN) - mean * mean;
    const float ri   = rsqrtf(var + 1e-12f);

    const float4* gp = (const float4*)gamma;
    const float4* bp = (const float4*)beta;
    float4* o = (float4*)(out + row * DIMN);
    #pragma unroll
    for (int j = 0; j < 6; j++) {
        float4 g4 = gp[lane + 32 * j], b4 = bp[lane + 32 * j], r;
        r.x = (v[j].x - mean) * ri * g4.x + b4.x;
        r.y = (v[j].y - mean) * ri * g4.y + b4.y;
        r.z = (v[j].z - mean) * ri * g4.z + b4.z;
        r.w = (v[j].w - mean) * ri * g4.w + b4.w;
        o[lane + 32 * j] = r;
    }
}

// ---------------- launch ------------------------------------------------------
#define SMEM_NT ((2 * ASZ + 2 * BSZ_NT) * 4)
#define SMEM_NN ((2 * ASZ + 2 * BSZ_NN) * 4)

extern "C" void kernel_launch(void* const* d_in, const int* in_sizes, int n_in,
                              void* d_out, int out_size) {
    const float* x   = (const float*)d_in[0];
    const float* Wq  = (const float*)d_in[1];
    const float* bq  = (const float*)d_in[2];
    const float* Wk  = (const float*)d_in[3];
    const float* bk  = (const float*)d_in[4];
    const float* Wv  = (const float*)d_in[5];
    const float* bv  = (const float*)d_in[6];
    const float* Wp  = (const float*)d_in[7];
    const float* bp  = (const float*)d_in[8];
    const float* g1  = (const float*)d_in[9];
    const float* be1 = (const float*)d_in[10];
    const float* W1  = (const float*)d_in[11];
    const float* b1  = (const float*)d_in[12];
    const float* W2  = (const float*)d_in[13];
    const float* b2  = (const float*)d_in[14];
    const float* g2  = (const float*)d_in[15];
    const float* be2 = (const float*)d_in[16];
    float* out = (float*)d_out;

    float *Q, *K, *V, *alpha, *attn, *t1, *h, *mlp, *t2;
    cudaGetSymbolAddress((void**)&Q, g_Q);
    cudaGetSymbolAddress((void**)&K, g_K);
    cudaGetSymbolAddress((void**)&V, g_V);
    cudaGetSymbolAddress((void**)&alpha, g_alpha);
    cudaGetSymbolAddress((void**)&attn, g_attn);
    cudaGetSymbolAddress((void**)&t1, g_t1);
    cudaGetSymbolAddress((void**)&h, g_h);
    cudaGetSymbolAddress((void**)&mlp, g_mlp);
    cudaGetSymbolAddress((void**)&t2, g_t2);

    cudaFuncSetAttribute(gemm_kernel<EPI_BIAS, true>,       cudaFuncAttributeMaxDynamicSharedMemorySize, SMEM_NT);
    cudaFuncSetAttribute(gemm_kernel<EPI_SCALE, true>,      cudaFuncAttributeMaxDynamicSharedMemorySize, SMEM_NT);
    cudaFuncSetAttribute(gemm_kernel<EPI_NONE, false>,      cudaFuncAttributeMaxDynamicSharedMemorySize, SMEM_NN);
    cudaFuncSetAttribute(gemm_kernel<EPI_BIAS_RESID, true>, cudaFuncAttributeMaxDynamicSharedMemorySize, SMEM_NT);
    cudaFuncSetAttribute(gemm_kernel<EPI_BIAS_GELU, true>,  cudaFuncAttributeMaxDynamicSharedMemorySize, SMEM_NT);

    dim3 blk(256);
    const long sQK = (long)NS * DIMN;     // per-batch stride of Q/K/V
    const long sAl = (long)NS * NS;       // per-batch stride of alpha

    // QKV projections: [16384,768] = x @ W^T + b
    gemm_kernel<EPI_BIAS, true><<<dim3(3, 128, 1), blk, SMEM_NT>>>(
        x, DIMN, 0, Wq, DIMN, 0, Q, DIMN, 0, bq, nullptr, DIMN);
    gemm_kernel<EPI_BIAS, true><<<dim3(3, 128, 1), blk, SMEM_NT>>>(
        x, DIMN, 0, Wk, DIMN, 0, K, DIMN, 0, bk, nullptr, DIMN);
    gemm_kernel<EPI_BIAS, true><<<dim3(3, 128, 1), blk, SMEM_NT>>>(
        x, DIMN, 0, Wv, DIMN, 0, V, DIMN, 0, bv, nullptr, DIMN);

    // alpha = Q @ K^T / sqrt(D)   (batched)
    gemm_kernel<EPI_SCALE, true><<<dim3(8, 16, NB), blk, SMEM_NT>>>(
        Q, DIMN, sQK, K, DIMN, sQK, alpha, NS, sAl, nullptr, nullptr, DIMN);

    // softmax rows
    softmax_kernel<<<NTOK, 256>>>(alpha);

    // attn = alpha @ V   (batched, NN)
    gemm_kernel<EPI_NONE, false><<<dim3(3, 16, NB), blk, SMEM_NN>>>(
        alpha, NS, sAl, V, DIMN, sQK, attn, DIMN, sQK, nullptr, nullptr, NS);

    // proj + residual: t1 = attn @ Wp^T + bp + x
    gemm_kernel<EPI_BIAS_RESID, true><<<dim3(3, 128, 1), blk, SMEM_NT>>>(
        attn, DIMN, 0, Wp, DIMN, 0, t1, DIMN, 0, bp, x, DIMN);

    // h = LN(t1)
    ln_kernel<<<NTOK / 4, 128>>>(t1, g1, be1, h);

    // mlp = gelu(h @ W1^T + b1)
    gemm_kernel<EPI_BIAS_GELU, true><<<dim3(6, 128, 1), blk, SMEM_NT>>>(
        h, DIMN, 0, W1, DIMN, 0, mlp, HIDN, 0, b1, nullptr, DIMN);

    // t2 = mlp @ W2^T + b2 + h
    gemm_kernel<EPI_BIAS_RESID, true><<<dim3(3, 128, 1), blk, SMEM_NT>>>(
        mlp, HIDN, 0, W2, HIDN, 0, t2, DIMN, 0, b2, h, HIDN);

    // out = LN(t2)
    ln_kernel<<<NTOK / 4, 128>>>(t2, g2, be2, out);
}

// round 4
// speedup vs baseline: 1.0196x; 1.0196x over previous
#include <cuda_runtime.h>
#include <cstdint>
#include <math.h>

#define DIMN 768
#define HIDN 1536
#define NB 8
#define NS 2048
#define NTOK (NB*NS)

#define INV_SCALE_F 0.03608439182435161f   // 1/sqrt(768)

static __device__ __forceinline__ float geluf(float x) {
    return 0.5f * x * (1.0f + erff(x * 0.70710678118654752f));
}

// ---------------- scratch (static device globals; allocation-free) ----------
__device__ float g_Q[(long)NTOK * DIMN];
__device__ float g_K[(long)NTOK * DIMN];
__device__ float g_V[(long)NTOK * DIMN];
__device__ float g_alpha[(long)NB * NS * NS];
__device__ float g_attn[(long)NTOK * DIMN];
__device__ float g_t1[(long)NTOK * DIMN];
__device__ float g_h[(long)NTOK * DIMN];
__device__ float g_mlp[(long)NTOK * HIDN];
__device__ float g_t2[(long)NTOK * DIMN];

// ---------------- small PTX helpers -----------------------------------------
__device__ __forceinline__ void cpa16(float* dst, const float* src) {
    unsigned d = (unsigned)__cvta_generic_to_shared(dst);
    asm volatile("cp.async.cg.shared.global [%0], [%1], 16;" :: "r"(d), "l"(src));
}
__device__ __forceinline__ void cp_commit() { asm volatile("cp.async.commit_group;"); }
template<int N> __device__ __forceinline__ void cp_wait() {
    asm volatile("cp.async.wait_group %0;" :: "n"(N));
}
__device__ __forceinline__ uint32_t f2tf32(float f) {
    uint32_t r; asm("cvt.rna.tf32.f32 %0, %1;" : "=r"(r) : "f"(f)); return r;
}
__device__ __forceinline__ void mma_tf32(float* c, const uint32_t* a, const uint32_t* b) {
    asm volatile(
        "mma.sync.aligned.m16n8k8.row.col.f32.tf32.tf32.f32 "
        "{%0,%1,%2,%3}, {%4,%5,%6,%7}, {%8,%9}, {%0,%1,%2,%3};"
        : "+f"(c[0]), "+f"(c[1]), "+f"(c[2]), "+f"(c[3])
        : "r"(a[0]), "r"(a[1]), "r"(a[2]), "r"(a[3]), "r"(b[0]), "r"(b[1]));
}

// ---------------- GEMM: C[M,N] = A[M,K] @ op(B) + epilogue -------------------
// BT=true : B stored [N,K] (use B^T)  — "NT"
// BT=false: B stored [K,N]            — "NN"
// CTA tile 128x256, 8 warps of 64x64, BK=64, 2-stage double buffer,
// register-level kk software pipeline.
enum { EPI_NONE = 0, EPI_SCALE = 1, EPI_BIAS = 2, EPI_BIAS_RESID = 3, EPI_BIAS_GELU = 4 };

#define BK 64
#define ALD 68
#define ASZ (128 * ALD)
#define BLDT 68
#define BSZ_NT (256 * BLDT)
#define BLDN 264
#define BSZ_NN (64 * BLDN)

template<bool BT>
__device__ __forceinline__ void load_tiles(const float* __restrict__ A, int lda,
                                           const float* __restrict__ Bg, int ldb,
                                           int m0, int n0, int kb,
                                           float* __restrict__ As, float* __restrict__ Bs,
                                           int tid) {
    // A tile: 128 rows x 64 k (row-major global) -> 2048 16B chunks
    {
        const float* src = A + (long)m0 * lda + kb * BK;
        #pragma unroll
        for (int i = 0; i < 8; i++) {
            int idx = tid + i * 256;
            int r = idx >> 4, c = (idx & 15) * 4;
            cpa16(As + r * ALD + c, src + (long)r * lda + c);
        }
    }
    if (BT) {
        // B tile: 256 n-rows x 64 k -> 4096 chunks
        const float* src = Bg + (long)n0 * ldb + kb * BK;
        #pragma unroll
        for (int i = 0; i < 16; i++) {
            int idx = tid + i * 256;
            int r = idx >> 4, c = (idx & 15) * 4;
            cpa16(Bs + r * BLDT + c, src + (long)r * ldb + c);
        }
    } else {
        // B tile: 64 k-rows x 256 n -> 4096 chunks
        const float* src = Bg + (long)(kb * BK) * ldb + n0;
        #pragma unroll
        for (int i = 0; i < 16; i++) {
            int idx = tid + i * 256;
            int r = idx >> 6, c = (idx & 63) * 4;
            cpa16(Bs + r * BLDN + c, src + (long)r * ldb + c);
        }
    }
}

template<bool BT>
__device__ __forceinline__ void frag_load(const float* __restrict__ Ab,
                                          const float* __restrict__ Bb,
                                          int wm0, int wn0, int g, int tg, int kk,
                                          uint32_t af[4][4], uint32_t bf[8][2]) {
    #pragma unroll
    for (int mi = 0; mi < 4; mi++) {
        const float* a = Ab + (wm0 + mi * 16 + g) * ALD + kk * 8 + tg;
        af[mi][0] = f2tf32(a[0]);
        af[mi][1] = f2tf32(a[8 * ALD]);
        af[mi][2] = f2tf32(a[4]);
        af[mi][3] = f2tf32(a[8 * ALD + 4]);
    }
    #pragma unroll
    for (int nj = 0; nj < 8; nj++) {
        if (BT) {
            const float* b = Bb + (wn0 + nj * 8 + g) * BLDT + kk * 8 + tg;
            bf[nj][0] = f2tf32(b[0]);
            bf[nj][1] = f2tf32(b[4]);
        } else {
            const float* b = Bb + (kk * 8 + tg) * BLDN + wn0 + nj * 8 + g;
            bf[nj][0] = f2tf32(b[0]);
            bf[nj][1] = f2tf32(b[4 * BLDN]);
        }
    }
}

template<int EPI, bool BT>
__global__ __launch_bounds__(256, 1)
void gemm_kernel(const float* __restrict__ A, int lda, long sA,
                 const float* __restrict__ Bg, int ldb, long sB,
                 float* __restrict__ C, int ldc, long sC,
                 const float* __restrict__ bias,
                 const float* __restrict__ resid,
                 int Kdim) {
    extern __shared__ float smem[];
    const int BSZ = BT ? BSZ_NT : BSZ_NN;
    float* As = smem;              // [2][ASZ]
    float* Bs = smem + 2 * ASZ;    // [2][BSZ]

    const int tid = threadIdx.x;
    const long bz = blockIdx.z;
    A += bz * sA; Bg += bz * sB; C += bz * sC;

    const int m0 = blockIdx.y * 128;
    const int n0 = blockIdx.x * 256;

    const int lane = tid & 31;
    const int g = lane >> 2, tg = lane & 3;
    const int wid = tid >> 5;
    const int wm0 = (wid & 1) * 64;
    const int wn0 = (wid >> 1) * 64;

    float acc[4][8][4];
    #pragma unroll
    for (int i = 0; i < 4; i++)
        #pragma unroll
        for (int j = 0; j < 8; j++)
            #pragma unroll
            for (int r = 0; r < 4; r++) acc[i][j][r] = 0.0f;

    const int nk = Kdim / BK;
    load_tiles<BT>(A, lda, Bg, ldb, m0, n0, 0, As, Bs, tid);
    cp_commit();
    load_tiles<BT>(A, lda, Bg, ldb, m0, n0, 1, As + ASZ, Bs + BSZ, tid);
    cp_commit();

    for (int kb = 0; kb < nk; ++kb) {
        if (kb + 1 < nk) cp_wait<1>(); else cp_wait<0>();
        __syncthreads();

        const float* Ab = As + (kb & 1) * ASZ;
        const float* Bb = Bs + (kb & 1) * BSZ;

        uint32_t af[2][4][4];
        uint32_t bf[2][8][2];
        frag_load<BT>(Ab, Bb, wm0, wn0, g, tg, 0, af[0], bf[0]);

        #pragma unroll
        for (int kk = 0; kk < 8; kk++) {
            const int cur = kk & 1;
            if (kk < 7)
                frag_load<BT>(Ab, Bb, wm0, wn0, g, tg, kk + 1, af[cur ^ 1], bf[cur ^ 1]);
            #pragma unroll
            for (int mi = 0; mi < 4; mi++)
                #pragma unroll
                for (int nj = 0; nj < 8; nj++)
                    mma_tf32(acc[mi][nj], af[cur][mi], bf[cur][nj]);
        }
        __syncthreads();

        if (kb + 2 < nk) {
            load_tiles<BT>(A, lda, Bg, ldb, m0, n0, kb + 2,
                           As + (kb & 1) * ASZ, Bs + (kb & 1) * BSZ, tid);
            cp_commit();
        }
    }

    // epilogue
    #pragma unroll
    for (int mi = 0; mi < 4; mi++) {
        #pragma unroll
        for (int r2 = 0; r2 < 2; r2++) {
            const int row = m0 + wm0 + mi * 16 + g + r2 * 8;
            #pragma unroll
            for (int nj = 0; nj < 8; nj++) {
                const int col = n0 + wn0 + nj * 8 + 2 * tg;
                float v0 = acc[mi][nj][r2 * 2 + 0];
                float v1 = acc[mi][nj][r2 * 2 + 1];
                const long off = (long)row * ldc + col;
                if (EPI == EPI_SCALE) { v0 *= INV_SCALE_F; v1 *= INV_SCALE_F; }
                if (EPI == EPI_BIAS || EPI == EPI_BIAS_RESID || EPI == EPI_BIAS_GELU) {
                    v0 += bias[col]; v1 += bias[col + 1];
                }
                if (EPI == EPI_BIAS_RESID) {
                    float2 rr = *(const float2*)(resid + off);
                    v0 += rr.x; v1 += rr.y;
                }
                if (EPI == EPI_BIAS_GELU) { v0 = geluf(v0); v1 = geluf(v1); }
                float2 o; o.x = v0; o.y = v1;
                *(float2*)(C + off) = o;
            }
        }
    }
}

// ---------------- softmax over rows of length 2048 ---------------------------
__global__ __launch_bounds__(256)
void softmax_kernel(float* __restrict__ a) {
    __shared__ float red[8];
    __shared__ float bc;
    const int t = threadIdx.x;
    const int lane = t & 31, wid = t >> 5;
    float* p = a + (long)blockIdx.x * 2048;

    float4 x0 = reinterpret_cast<float4*>(p)[t];
    float4 x1 = reinterpret_cast<float4*>(p)[t + 256];

    float m = fmaxf(fmaxf(fmaxf(x0.x, x0.y), fmaxf(x0.z, x0.w)),
                    fmaxf(fmaxf(x1.x, x1.y), fmaxf(x1.z, x1.w)));
    #pragma unroll
    for (int o = 16; o > 0; o >>= 1) m = fmaxf(m, __shfl_xor_sync(0xffffffffu, m, o));
    if (lane == 0) red[wid] = m;
    __syncthreads();
    if (t == 0) {
        float mm = red[0];
        #pragma unroll
        for (int i = 1; i < 8; i++) mm = fmaxf(mm, red[i]);
        bc = mm;
    }
    __syncthreads();
    m = bc;

    float e[8];
    e[0] = __expf(x0.x - m); e[1] = __expf(x0.y - m);
    e[2] = __expf(x0.z - m); e[3] = __expf(x0.w - m);
    e[4] = __expf(x1.x - m); e[5] = __expf(x1.y - m);
    e[6] = __expf(x1.z - m); e[7] = __expf(x1.w - m);
    float s = (e[0] + e[1]) + (e[2] + e[3]) + (e[4] + e[5]) + (e[6] + e[7]);
    #pragma unroll
    for (int o = 16; o > 0; o >>= 1) s += __shfl_xor_sync(0xffffffffu, s, o);
    if (lane == 0) red[wid] = s;
    __syncthreads();
    if (t == 0) {
        float ss = 0.0f;
        #pragma unroll
        for (int i = 0; i < 8; i++) ss += red[i];
        bc = 1.0f / ss;
    }
    __syncthreads();
    const float inv = bc;

    x0.x = e[0] * inv; x0.y = e[1] * inv; x0.z = e[2] * inv; x0.w = e[3] * inv;
    x1.x = e[4] * inv; x1.y = e[5] * inv; x1.z = e[6] * inv; x1.w = e[7] * inv;
    reinterpret_cast<float4*>(p)[t]       = x0;
    reinterpret_cast<float4*>(p)[t + 256] = x1;
}

// ---------------- LayerNorm over rows of 768 (one warp per row) --------------
__global__ __launch_bounds__(128)
void ln_kernel(const float* __restrict__ in, const float* __restrict__ gamma,
               const float* __restrict__ beta, float* __restrict__ out) {
    const int wid = threadIdx.x >> 5, lane = threadIdx.x & 31;
    const long row = (long)blockIdx.x * 4 + wid;
    const float4* p = (const float4*)(in + row * DIMN);

    float4 v[6];
    float s = 0.0f, sq = 0.0f;
    #pragma unroll
    for (int j = 0; j < 6; j++) {
        v[j] = p[lane + 32 * j];
        s  += (v[j].x + v[j].y) + (v[j].z + v[j].w);
        sq += (v[j].x * v[j].x + v[j].y * v[j].y) + (v[j].z * v[j].z + v[j].w * v[j].w);
    }
    #pragma unroll
    for (int o = 16; o > 0; o >>= 1) {
        s  += __shfl_xor_sync(0xffffffffu, s, o);
        sq += __shfl_xor_sync(0xffffffffu, sq, o);
    }
    const float mean = s * (1.0f / DIMN);
    const float var  = sq * (1.0f / DIMN) - mean * mean;
    const float ri   = rsqrtf(var + 1e-12f);

    const float4* gp = (const float4*)gamma;
    const float4* bp = (const float4*)beta;
    float4* o = (float4*)(out + row * DIMN);
    #pragma unroll
    for (int j = 0; j < 6; j++) {
        float4 g4 = gp[lane + 32 * j], b4 = bp[lane + 32 * j], r;
        r.x = (v[j].x - mean) * ri * g4.x + b4.x;
        r.y = (v[j].y - mean) * ri * g4.y + b4.y;
        r.z = (v[j].z - mean) * ri * g4.z + b4.z;
        r.w = (v[j].w - mean) * ri * g4.w + b4.w;
        o[lane + 32 * j] = r;
    }
}

// ---------------- launch ------------------------------------------------------
#define SMEM_NT ((2 * ASZ + 2 * BSZ_NT) * 4)
#define SMEM_NN ((2 * ASZ + 2 * BSZ_NN) * 4)

extern "C" void kernel_launch(void* const* d_in, const int* in_sizes, int n_in,
                              void* d_out, int out_size) {
    const float* x   = (const float*)d_in[0];
    const float* Wq  = (const float*)d_in[1];
    const float* bq  = (const float*)d_in[2];
    const float* Wk  = (const float*)d_in[3];
    const float* bk  = (const float*)d_in[4];
    const float* Wv  = (const float*)d_in[5];
    const float* bv  = (const float*)d_in[6];
    const float* Wp  = (const float*)d_in[7];
    const float* bp  = (const float*)d_in[8];
    const float* g1  = (const float*)d_in[9];
    const float* be1 = (const float*)d_in[10];
    const float* W1  = (const float*)d_in[11];
    const float* b1  = (const float*)d_in[12];
    const float* W2  = (const float*)d_in[13];
    const float* b2  = (const float*)d_in[14];
    const float* g2  = (const float*)d_in[15];
    const float* be2 = (const float*)d_in[16];
    float* out = (float*)d_out;

    float *Q, *K, *V, *alpha, *attn, *t1, *h, *mlp, *t2;
    cudaGetSymbolAddress((void**)&Q, g_Q);
    cudaGetSymbolAddress((void**)&K, g_K);
    cudaGetSymbolAddress((void**)&V, g_V);
    cudaGetSymbolAddress((void**)&alpha, g_alpha);
    cudaGetSymbolAddress((void**)&attn, g_attn);
    cudaGetSymbolAddress((void**)&t1, g_t1);
    cudaGetSymbolAddress((void**)&h, g_h);
    cudaGetSymbolAddress((void**)&mlp, g_mlp);
    cudaGetSymbolAddress((void**)&t2, g_t2);

    cudaFuncSetAttribute(gemm_kernel<EPI_BIAS, true>,       cudaFuncAttributeMaxDynamicSharedMemorySize, SMEM_NT);
    cudaFuncSetAttribute(gemm_kernel<EPI_SCALE, true>,      cudaFuncAttributeMaxDynamicSharedMemorySize, SMEM_NT);
    cudaFuncSetAttribute(gemm_kernel<EPI_NONE, false>,      cudaFuncAttributeMaxDynamicSharedMemorySize, SMEM_NN);
    cudaFuncSetAttribute(gemm_kernel<EPI_BIAS_RESID, true>, cudaFuncAttributeMaxDynamicSharedMemorySize, SMEM_NT);
    cudaFuncSetAttribute(gemm_kernel<EPI_BIAS_GELU, true>,  cudaFuncAttributeMaxDynamicSharedMemorySize, SMEM_NT);

    dim3 blk(256);
    const long sQK = (long)NS * DIMN;     // per-batch stride of Q/K/V
    const long sAl = (long)NS * NS;       // per-batch stride of alpha

    // QKV projections: [16384,768] = x @ W^T + b
    gemm_kernel<EPI_BIAS, true><<<dim3(3, 128, 1), blk, SMEM_NT>>>(
        x, DIMN, 0, Wq, DIMN, 0, Q, DIMN, 0, bq, nullptr, DIMN);
    gemm_kernel<EPI_BIAS, true><<<dim3(3, 128, 1), blk, SMEM_NT>>>(
        x, DIMN, 0, Wk, DIMN, 0, K, DIMN, 0, bk, nullptr, DIMN);
    gemm_kernel<EPI_BIAS, true><<<dim3(3, 128, 1), blk, SMEM_NT>>>(
        x, DIMN, 0, Wv, DIMN, 0, V, DIMN, 0, bv, nullptr, DIMN);

    // alpha = Q @ K^T / sqrt(D)   (batched)
    gemm_kernel<EPI_SCALE, true><<<dim3(8, 16, NB), blk, SMEM_NT>>>(
        Q, DIMN, sQK, K, DIMN, sQK, alpha, NS, sAl, nullptr, nullptr, DIMN);

    // softmax rows
    softmax_kernel<<<NTOK, 256>>>(alpha);

    // attn = alpha @ V   (batched, NN)
    gemm_kernel<EPI_NONE, false><<<dim3(3, 16, NB), blk, SMEM_NN>>>(
        alpha, NS, sAl, V, DIMN, sQK, attn, DIMN, sQK, nullptr, nullptr, NS);

    // proj + residual: t1 = attn @ Wp^T + bp + x
    gemm_kernel<EPI_BIAS_RESID, true><<<dim3(3, 128, 1), blk, SMEM_NT>>>(
        attn, DIMN, 0, Wp, DIMN, 0, t1, DIMN, 0, bp, x, DIMN);

    // h = LN(t1)
    ln_kernel<<<NTOK / 4, 128>>>(t1, g1, be1, h);

    // mlp = gelu(h @ W1^T + b1)
    gemm_kernel<EPI_BIAS_GELU, true><<<dim3(6, 128, 1), blk, SMEM_NT>>>(
        h, DIMN, 0, W1, DIMN, 0, mlp, HIDN, 0, b1, nullptr, DIMN);

    // t2 = mlp @ W2^T + b2 + h
    gemm_kernel<EPI_BIAS_RESID, true><<<dim3(3, 128, 1), blk, SMEM_NT>>>(
        mlp, HIDN, 0, W2, HIDN, 0, t2, DIMN, 0, b2, h, HIDN);

    // out = LN(t2)
    ln_kernel<<<NTOK / 4, 128>>>(t2, g2, be2, out);
}